// round 3
// baseline (speedup 1.0000x reference)
#include <cuda_runtime.h>
#include <cuda_bf16.h>

// Problem constants (fixed by the reference):
//   S=4096, H=3, E=512, G=3334, F=1, integral_resolution = 0.03
// out = sum_{s,h,e} mask * (base_h + w_h*feat)  -  0.03 * sum_{s,h,g} exp(base_h + w_h*grid)

#define S_DIM 4096
#define H_DIM 3
#define E_DIM 512
#define G_DIM 3334

constexpr int N_EV = S_DIM * H_DIM * E_DIM;   // 6,291,456
constexpr int N_GR = S_DIM * H_DIM * G_DIM;   // 40,968,192
constexpr int N_EV4 = N_EV / 4;               // 1,572,864 (E=512 divisible by 4; h constant within a float4)
constexpr int N_GR2 = N_GR / 2;               // 20,484,096 (G=3334 even; h constant within a float2)
constexpr int G_HALF = G_DIM / 2;             // 1667

constexpr int NBLK = 1184;                    // 148 SMs * 8
constexpr int NTHR = 256;

__device__ float g_part_log[NBLK];
__device__ float g_part_int[NBLK];

__global__ void __launch_bounds__(NTHR, 8) lm_main_kernel(
    const float* __restrict__ ev_feat,
    const int* __restrict__ ev_mask,      // bool -> int32 in the harness
    const float* __restrict__ gr_feat,
    const float* __restrict__ weights,
    const float* __restrict__ bases,
    const float* __restrict__ effects)
{
    const float b0 = bases[0], b1 = bases[1], b2 = bases[2];
    const float w0 = weights[0] * effects[0];
    const float w1 = weights[1] * effects[1];
    const float w2 = weights[2] * effects[2];

    const int tid = blockIdx.x * NTHR + threadIdx.x;
    const int stride = NBLK * NTHR;

    float plog = 0.0f;
    float pint = 0.0f;

    // ---- Event part: masked sum of (base_h + w_h * feat) ----
    const float4* __restrict__ ev4 = (const float4*)ev_feat;
    const int4*   __restrict__ m4  = (const int4*)ev_mask;
    for (int j = tid; j < N_EV4; j += stride) {
        const int i = j << 2;                 // element index
        const int h = (i >> 9) % 3;           // E=512 -> row = i>>9, h = row % 3
        const float bb = (h == 0) ? b0 : ((h == 1) ? b1 : b2);
        const float ww = (h == 0) ? w0 : ((h == 1) ? w1 : w2);
        const float4 f = ev4[j];
        const int4   m = m4[j];
        if (m.x) plog += fmaf(ww, f.x, bb);
        if (m.y) plog += fmaf(ww, f.y, bb);
        if (m.z) plog += fmaf(ww, f.z, bb);
        if (m.w) plog += fmaf(ww, f.w, bb);
    }

    // ---- Grid part: sum of exp(base_h + w_h * g) ----
    const float2* __restrict__ gr2 = (const float2*)gr_feat;
    for (int j = tid; j < N_GR2; j += stride) {
        const int h = (j / G_HALF) % 3;       // row = j / 1667 (float2 units), h = row % 3
        const float bb = (h == 0) ? b0 : ((h == 1) ? b1 : b2);
        const float ww = (h == 0) ? w0 : ((h == 1) ? w1 : w2);
        const float2 g = gr2[j];
        pint += __expf(fmaf(ww, g.x, bb));
        pint += __expf(fmaf(ww, g.y, bb));
    }

    // ---- Block reduction ----
    __shared__ float s_log[NTHR / 32];
    __shared__ float s_int[NTHR / 32];
    const int lane = threadIdx.x & 31;
    const int wid  = threadIdx.x >> 5;
    #pragma unroll
    for (int off = 16; off > 0; off >>= 1) {
        plog += __shfl_xor_sync(0xFFFFFFFFu, plog, off);
        pint += __shfl_xor_sync(0xFFFFFFFFu, pint, off);
    }
    if (lane == 0) { s_log[wid] = plog; s_int[wid] = pint; }
    __syncthreads();
    if (wid == 0) {
        float vl = (lane < NTHR / 32) ? s_log[lane] : 0.0f;
        float vi = (lane < NTHR / 32) ? s_int[lane] : 0.0f;
        #pragma unroll
        for (int off = 4; off > 0; off >>= 1) {
            vl += __shfl_xor_sync(0xFFFFFFFFu, vl, off);
            vi += __shfl_xor_sync(0xFFFFFFFFu, vi, off);
        }
        if (lane == 0) {
            g_part_log[blockIdx.x] = vl;
            g_part_int[blockIdx.x] = vi;
        }
    }
}

__global__ void __launch_bounds__(256) lm_final_kernel(float* __restrict__ out)
{
    // Deterministic final reduction in double (trivial op count).
    __shared__ double s_log[8];
    __shared__ double s_int[8];
    double dl = 0.0, di = 0.0;
    for (int j = threadIdx.x; j < NBLK; j += 256) {
        dl += (double)g_part_log[j];
        di += (double)g_part_int[j];
    }
    const int lane = threadIdx.x & 31;
    const int wid  = threadIdx.x >> 5;
    #pragma unroll
    for (int off = 16; off > 0; off >>= 1) {
        dl += __shfl_xor_sync(0xFFFFFFFFu, dl, off);
        di += __shfl_xor_sync(0xFFFFFFFFu, di, off);
    }
    if (lane == 0) { s_log[wid] = dl; s_int[wid] = di; }
    __syncthreads();
    if (threadIdx.x == 0) {
        double tl = 0.0, ti = 0.0;
        #pragma unroll
        for (int k = 0; k < 8; k++) { tl += s_log[k]; ti += s_int[k]; }
        out[0] = (float)(tl - 0.03 * ti);
    }
}

extern "C" void kernel_launch(void* const* d_in, const int* in_sizes, int n_in,
                              void* d_out, int out_size)
{
    const float* ev_feat = (const float*)d_in[0];
    const int*   ev_mask = (const int*)d_in[1];
    const float* gr_feat = (const float*)d_in[2];
    const float* weights = (const float*)d_in[3];
    const float* bases   = (const float*)d_in[4];
    const float* effects = (const float*)d_in[5];
    float* out = (float*)d_out;

    lm_main_kernel<<<NBLK, NTHR>>>(ev_feat, ev_mask, gr_feat, weights, bases, effects);
    lm_final_kernel<<<1, 256>>>(out);
}

// round 4
// speedup vs baseline: 1.0538x; 1.0538x over previous
#include <cuda_runtime.h>
#include <cuda_bf16.h>

// Problem constants (fixed by the reference):
//   S=4096, H=3, E=512, G=3334, F=1, integral_resolution = 0.03
// out = sum_{s,h,e} mask * (base_h + w_h*feat)  -  0.03 * sum_{s,h,g} exp(base_h + w_h*grid)

#define S_DIM 4096
#define H_DIM 3
#define E_DIM 512
#define G_DIM 3334

constexpr int N_EV  = S_DIM * H_DIM * E_DIM;  // 6,291,456
constexpr int N_GR  = S_DIM * H_DIM * G_DIM;  // 40,968,192
constexpr int N_EV4 = N_EV / 4;               // 1,572,864 (h constant within a float4: E=512)
constexpr int N_GR2 = N_GR / 2;               // 20,484,096 (h constant within a float2: G even)
constexpr int G_HALF = G_DIM / 2;             // 1667

constexpr int NBLK = 1184;                    // 148 SMs * 8
constexpr int NTHR = 256;

__device__ float g_part_log[NBLK];
__device__ float g_part_int[NBLK];
__device__ unsigned int g_done_count = 0;

__global__ void __launch_bounds__(NTHR, 8) lm_fused_kernel(
    const float* __restrict__ ev_feat,
    const int* __restrict__ ev_mask,      // bool -> int32 in the harness
    const float* __restrict__ gr_feat,
    const float* __restrict__ weights,
    const float* __restrict__ bases,
    const float* __restrict__ effects,
    float* __restrict__ out)
{
    const float b0 = bases[0], b1 = bases[1], b2 = bases[2];
    const float w0 = weights[0] * effects[0];
    const float w1 = weights[1] * effects[1];
    const float w2 = weights[2] * effects[2];

    const int tid = blockIdx.x * NTHR + threadIdx.x;
    const int stride = NBLK * NTHR;

    float plog = 0.0f;
    float pint = 0.0f;

    // ---- Event part: masked sum of (base_h + w_h * feat), unroll x2 for MLP ----
    const float4* __restrict__ ev4 = (const float4*)ev_feat;
    const int4*   __restrict__ m4  = (const int4*)ev_mask;
    {
        int j = tid;
        for (; j + stride < N_EV4; j += 2 * stride) {
            const float4 f0 = ev4[j];
            const int4   a0 = m4[j];
            const float4 f1 = ev4[j + stride];
            const int4   a1 = m4[j + stride];

            int h = ((j << 2) >> 9) % 3;
            float bb = (h == 0) ? b0 : ((h == 1) ? b1 : b2);
            float ww = (h == 0) ? w0 : ((h == 1) ? w1 : w2);
            if (a0.x) plog += fmaf(ww, f0.x, bb);
            if (a0.y) plog += fmaf(ww, f0.y, bb);
            if (a0.z) plog += fmaf(ww, f0.z, bb);
            if (a0.w) plog += fmaf(ww, f0.w, bb);

            h = (((j + stride) << 2) >> 9) % 3;
            bb = (h == 0) ? b0 : ((h == 1) ? b1 : b2);
            ww = (h == 0) ? w0 : ((h == 1) ? w1 : w2);
            if (a1.x) plog += fmaf(ww, f1.x, bb);
            if (a1.y) plog += fmaf(ww, f1.y, bb);
            if (a1.z) plog += fmaf(ww, f1.z, bb);
            if (a1.w) plog += fmaf(ww, f1.w, bb);
        }
        for (; j < N_EV4; j += stride) {
            const int h = ((j << 2) >> 9) % 3;
            const float bb = (h == 0) ? b0 : ((h == 1) ? b1 : b2);
            const float ww = (h == 0) ? w0 : ((h == 1) ? w1 : w2);
            const float4 f = ev4[j];
            const int4   m = m4[j];
            if (m.x) plog += fmaf(ww, f.x, bb);
            if (m.y) plog += fmaf(ww, f.y, bb);
            if (m.z) plog += fmaf(ww, f.z, bb);
            if (m.w) plog += fmaf(ww, f.w, bb);
        }
    }

    // ---- Grid part: sum of exp(base_h + w_h * g), unroll x4 for MLP ----
    const float2* __restrict__ gr2 = (const float2*)gr_feat;
    {
        int j = tid;
        for (; j + 3 * stride < N_GR2; j += 4 * stride) {
            const float2 ga = gr2[j];
            const float2 gb = gr2[j + stride];
            const float2 gc = gr2[j + 2 * stride];
            const float2 gd = gr2[j + 3 * stride];

            int h; float bb, ww;
            h = (j / G_HALF) % 3;
            bb = (h == 0) ? b0 : ((h == 1) ? b1 : b2);
            ww = (h == 0) ? w0 : ((h == 1) ? w1 : w2);
            pint += __expf(fmaf(ww, ga.x, bb)) + __expf(fmaf(ww, ga.y, bb));

            h = ((j + stride) / G_HALF) % 3;
            bb = (h == 0) ? b0 : ((h == 1) ? b1 : b2);
            ww = (h == 0) ? w0 : ((h == 1) ? w1 : w2);
            pint += __expf(fmaf(ww, gb.x, bb)) + __expf(fmaf(ww, gb.y, bb));

            h = ((j + 2 * stride) / G_HALF) % 3;
            bb = (h == 0) ? b0 : ((h == 1) ? b1 : b2);
            ww = (h == 0) ? w0 : ((h == 1) ? w1 : w2);
            pint += __expf(fmaf(ww, gc.x, bb)) + __expf(fmaf(ww, gc.y, bb));

            h = ((j + 3 * stride) / G_HALF) % 3;
            bb = (h == 0) ? b0 : ((h == 1) ? b1 : b2);
            ww = (h == 0) ? w0 : ((h == 1) ? w1 : w2);
            pint += __expf(fmaf(ww, gd.x, bb)) + __expf(fmaf(ww, gd.y, bb));
        }
        for (; j < N_GR2; j += stride) {
            const int h = (j / G_HALF) % 3;
            const float bb = (h == 0) ? b0 : ((h == 1) ? b1 : b2);
            const float ww = (h == 0) ? w0 : ((h == 1) ? w1 : w2);
            const float2 g = gr2[j];
            pint += __expf(fmaf(ww, g.x, bb)) + __expf(fmaf(ww, g.y, bb));
        }
    }

    // ---- Block reduction ----
    __shared__ float s_log[NTHR / 32];
    __shared__ float s_int[NTHR / 32];
    __shared__ bool s_is_last;
    const int lane = threadIdx.x & 31;
    const int wid  = threadIdx.x >> 5;
    #pragma unroll
    for (int off = 16; off > 0; off >>= 1) {
        plog += __shfl_xor_sync(0xFFFFFFFFu, plog, off);
        pint += __shfl_xor_sync(0xFFFFFFFFu, pint, off);
    }
    if (lane == 0) { s_log[wid] = plog; s_int[wid] = pint; }
    __syncthreads();
    if (wid == 0) {
        float vl = (lane < NTHR / 32) ? s_log[lane] : 0.0f;
        float vi = (lane < NTHR / 32) ? s_int[lane] : 0.0f;
        #pragma unroll
        for (int off = 4; off > 0; off >>= 1) {
            vl += __shfl_xor_sync(0xFFFFFFFFu, vl, off);
            vi += __shfl_xor_sync(0xFFFFFFFFu, vi, off);
        }
        if (lane == 0) {
            g_part_log[blockIdx.x] = vl;
            g_part_int[blockIdx.x] = vi;
            __threadfence();
            unsigned int ticket = atomicAdd(&g_done_count, 1u);
            s_is_last = (ticket == (unsigned int)(NBLK - 1));
        }
    }
    __syncthreads();

    // ---- Last block: deterministic final combine in double ----
    if (s_is_last) {
        __shared__ double d_log[NTHR / 32];
        __shared__ double d_int[NTHR / 32];
        double dl = 0.0, di = 0.0;
        for (int j = threadIdx.x; j < NBLK; j += NTHR) {
            dl += (double)g_part_log[j];
            di += (double)g_part_int[j];
        }
        #pragma unroll
        for (int off = 16; off > 0; off >>= 1) {
            dl += __shfl_xor_sync(0xFFFFFFFFu, dl, off);
            di += __shfl_xor_sync(0xFFFFFFFFu, di, off);
        }
        if (lane == 0) { d_log[wid] = dl; d_int[wid] = di; }
        __syncthreads();
        if (threadIdx.x == 0) {
            double tl = 0.0, ti = 0.0;
            #pragma unroll
            for (int k = 0; k < NTHR / 32; k++) { tl += d_log[k]; ti += d_int[k]; }
            out[0] = (float)(tl - 0.03 * ti);
            g_done_count = 0;   // reset for next graph replay
        }
    }
}

extern "C" void kernel_launch(void* const* d_in, const int* in_sizes, int n_in,
                              void* d_out, int out_size)
{
    const float* ev_feat = (const float*)d_in[0];
    const int*   ev_mask = (const int*)d_in[1];
    const float* gr_feat = (const float*)d_in[2];
    const float* weights = (const float*)d_in[3];
    const float* bases   = (const float*)d_in[4];
    const float* effects = (const float*)d_in[5];
    float* out = (float*)d_out;

    lm_fused_kernel<<<NBLK, NTHR>>>(ev_feat, ev_mask, gr_feat, weights, bases, effects, out);
}